// round 5
// baseline (speedup 1.0000x reference)
#include <cuda_runtime.h>
#include <stdint.h>
#include <math.h>

#define HD   2048
#define BDIM 8192
#define BM   128
#define BN   256
#define BK   32
#define NST  3
#define SA_ST 36    // floats; conflict-free A frag loads (4r+kc mod 32)
#define SB_ST 264   // floats; conflict-free B frag loads (8kc+c mod 32)
#define SA_FLOATS (BM * SA_ST)               // 4608
#define SB_FLOATS (BK * SB_ST)               // 8448
#define SMEM_BYTES ((NST * (SA_FLOATS + SB_FLOATS)) * 4)  // 156672

// ---------------- device scratch ----------------
__device__ float g_S1[(size_t)BDIM * 8192];   // [z | r | u | cand_x]
__device__ float g_S2[(size_t)BDIM * 6144];   // [z2 | r2 | cand2]
__device__ float g_hd[(size_t)BDIM * HD];     // h_new - h

// ---------------- PTX helpers ----------------
#define CP_ASYNC(dst, src) \
    asm volatile("cp.async.cg.shared.global [%0], [%1], 16;" :: "r"(dst), "l"(src))
#define CP_COMMIT() asm volatile("cp.async.commit_group;" ::: "memory")
#define CP_WAIT(n)  asm volatile("cp.async.wait_group %0;" :: "n"(n) : "memory")

__device__ __forceinline__ void mma8(float c[4], const uint32_t a[4], const uint32_t b[2]) {
    asm volatile(
        "mma.sync.aligned.m16n8k8.row.col.f32.tf32.tf32.f32 "
        "{%0,%1,%2,%3}, {%4,%5,%6,%7}, {%8,%9}, {%0,%1,%2,%3};\n"
        : "+f"(c[0]), "+f"(c[1]), "+f"(c[2]), "+f"(c[3])
        : "r"(a[0]), "r"(a[1]), "r"(a[2]), "r"(a[3]), "r"(b[0]), "r"(b[1]));
}

// ---------------- GEMM args ----------------
struct GArgs {
    float* C;
    long long ldc;
    int nA[4];
    const float* A[4][3];
    const float* W[4][3];
    long long ldw[4][3];
    const float* bias[4][3];
};

// grid: x = M tiles (64), y = N tiles. blk = y>>3 (gate block), nloc = (y&7)*256
__global__ __launch_bounds__(256, 1)
void gemm_tf32_kernel(const __grid_constant__ GArgs args) {
    extern __shared__ float smem[];
    float* sA = smem;                      // [NST][SA_FLOATS]
    float* sB = smem + NST * SA_FLOATS;    // [NST][SB_FLOATS]

    const int tid  = threadIdx.x;
    const int lane = tid & 31;
    const int warp = tid >> 5;
    const int wm = warp & 1;    // 2 warps along M (64 rows)
    const int wn = warp >> 1;   // 4 warps along N (64 cols)

    const int m0   = blockIdx.x << 7;
    const int blk  = blockIdx.y >> 3;
    const int nloc = (blockIdx.y & 7) << 8;
    const int nA   = args.nA[blk];
    const int iters = nA << 6;              // nA * (2048/32)

    const float* Ap[3];
    const float* Wp[3];
    long long ldw[3];
#pragma unroll
    for (int a = 0; a < 3; a++) {
        Ap[a] = args.A[blk][a];
        Wp[a] = args.W[blk][a];
        ldw[a] = args.ldw[blk][a];
    }

    float acc[4][8][4];
#pragma unroll
    for (int i = 0; i < 4; i++)
#pragma unroll
        for (int j = 0; j < 8; j++)
#pragma unroll
            for (int k = 0; k < 4; k++) acc[i][j][k] = 0.f;

    // ---- async load mapping ----
    const int arow = tid >> 3;            // 0..31 (A rows, +32*i)
    const int acol = (tid & 7) << 2;      // 0..28
    const int brow = tid >> 6;            // 0..3  (B rows, +4*i)
    const int bcol = (tid & 63) << 2;     // 0..252

    auto load_stage = [&](int it) {
        const int s = it % NST;
        const int a = it >> 6;
        const int k0 = (it & 63) << 5;
        const float* Abase = Ap[a] + (size_t)m0 * HD + k0;
        const float* Wbase = Wp[a] + (size_t)k0 * ldw[a] + nloc;
        float* dA = sA + s * SA_FLOATS;
        float* dB = sB + s * SB_FLOATS;
#pragma unroll
        for (int i = 0; i < 4; i++) {
            const int r = arow + i * 32;
            uint32_t dst = (uint32_t)__cvta_generic_to_shared(dA + r * SA_ST + acol);
            CP_ASYNC(dst, Abase + (size_t)r * HD + acol);
        }
#pragma unroll
        for (int i = 0; i < 8; i++) {
            const int r = brow + i * 4;
            uint32_t dst = (uint32_t)__cvta_generic_to_shared(dB + r * SB_ST + bcol);
            CP_ASYNC(dst, Wbase + (size_t)r * ldw[a] + bcol);
        }
        CP_COMMIT();
    };

    // fragment load for one ks (K=8 chunk)
    auto load_frags = [&](const float* cA, const float* cB, int ks,
                          uint32_t (&af)[4][4], uint32_t (&bf)[8][2]) {
        const int kc = ks * 8 + (lane & 3);
#pragma unroll
        for (int mt = 0; mt < 4; mt++) {
            const int r = wm * 64 + mt * 16 + (lane >> 2);
            af[mt][0] = __float_as_uint(cA[r * SA_ST + kc]);
            af[mt][1] = __float_as_uint(cA[(r + 8) * SA_ST + kc]);
            af[mt][2] = __float_as_uint(cA[r * SA_ST + kc + 4]);
            af[mt][3] = __float_as_uint(cA[(r + 8) * SA_ST + kc + 4]);
        }
#pragma unroll
        for (int nt = 0; nt < 8; nt++) {
            const int c = wn * 64 + nt * 8 + (lane >> 2);
            bf[nt][0] = __float_as_uint(cB[kc * SB_ST + c]);
            bf[nt][1] = __float_as_uint(cB[(kc + 4) * SB_ST + c]);
        }
    };

    auto compute = [&](int s) {
        const float* cA = sA + s * SA_FLOATS;
        const float* cB = sB + s * SB_FLOATS;
        uint32_t afb[2][4][4], bfb[2][8][2];
        load_frags(cA, cB, 0, afb[0], bfb[0]);
#pragma unroll
        for (int ks = 0; ks < 4; ks++) {
            const int cur = ks & 1;
            if (ks < 3) load_frags(cA, cB, ks + 1, afb[cur ^ 1], bfb[cur ^ 1]);
#pragma unroll
            for (int mt = 0; mt < 4; mt++)
#pragma unroll
                for (int nt = 0; nt < 8; nt++)
                    mma8(acc[mt][nt], afb[cur][mt], bfb[cur][nt]);
        }
    };

    load_stage(0);
    load_stage(1);

#pragma unroll 1
    for (int it = 0; it < iters; it++) {
        CP_WAIT(1);
        __syncthreads();
        if (it + 2 < iters) load_stage(it + 2);
        compute(it % NST);
    }

    // epilogue: bias + store
    const int cbase = blockIdx.y << 8;
#pragma unroll
    for (int nt = 0; nt < 8; nt++) {
        const int cl = wn * 64 + nt * 8 + 2 * (lane & 3);
        float bs0 = 0.f, bs1 = 0.f;
        for (int a = 0; a < nA; a++) {
            bs0 += args.bias[blk][a][nloc + cl];
            bs1 += args.bias[blk][a][nloc + cl + 1];
        }
#pragma unroll
        for (int mt = 0; mt < 4; mt++) {
            const int r = m0 + wm * 64 + mt * 16 + (lane >> 2);
            float2 v0 = make_float2(acc[mt][nt][0] + bs0, acc[mt][nt][1] + bs1);
            float2 v1 = make_float2(acc[mt][nt][2] + bs0, acc[mt][nt][3] + bs1);
            *(float2*)(args.C + (size_t)r * args.ldc + cbase + cl) = v0;
            *(float2*)(args.C + (size_t)(r + 8) * args.ldc + cbase + cl) = v1;
        }
    }
}

// ---------------- elementwise epilogues ----------------
__device__ __forceinline__ float sigm(float x) { return 1.f / (1.f + expf(-x)); }

__global__ void epi1_kernel(const float* __restrict__ h, const float* __restrict__ g,
                            float* __restrict__ hnew) {
    size_t e0 = ((size_t)blockIdx.x * blockDim.x + threadIdx.x) * 4;
    size_t b = e0 >> 11, j = e0 & 2047;
    const float* row = g_S1 + b * 8192 + j;
    float4 zp = *(const float4*)(row);
    float4 rp = *(const float4*)(row + 2048);
    float4 up = *(const float4*)(row + 4096);
    float4 cp = *(const float4*)(row + 6144);
    float4 hv = *(const float4*)(h + e0);
    float4 gv = *(const float4*)(g + e0);
    float4 hn, hd;
#define DO1(f)                                                     \
    {                                                              \
        float z = sigm(zp.f), r = sigm(rp.f), uu = sigm(up.f);     \
        float cand = tanhf(cp.f + r * hv.f + uu * gv.f);           \
        hn.f = (1.f - z) * hv.f + z * cand;                        \
        hd.f = hn.f - hv.f;                                        \
    }
    DO1(x) DO1(y) DO1(z) DO1(w)
#undef DO1
    *(float4*)(hnew + e0) = hn;
    *(float4*)(g_hd + e0) = hd;
}

__global__ void epi2_kernel(const float* __restrict__ g, float* __restrict__ gnew) {
    size_t e0 = ((size_t)blockIdx.x * blockDim.x + threadIdx.x) * 4;
    size_t b = e0 >> 11, j = e0 & 2047;
    const float* row = g_S2 + b * 6144 + j;
    float4 zp = *(const float4*)(row);
    float4 rp = *(const float4*)(row + 2048);
    float4 cp = *(const float4*)(row + 4096);
    float4 gv = *(const float4*)(g + e0);
    float4 gn;
#define DO2(f)                                       \
    {                                                \
        float z = sigm(zp.f), r = sigm(rp.f);        \
        float cand = tanhf(cp.f + r * gv.f);         \
        gn.f = (1.f - z) * gv.f + z * cand;          \
    }
    DO2(x) DO2(y) DO2(z) DO2(w)
#undef DO2
    *(float4*)(gnew + e0) = gn;
}

// ---------------- host ----------------
extern "C" void kernel_launch(void* const* d_in, const int* in_sizes, int n_in,
                              void* d_out, int out_size) {
    (void)in_sizes; (void)n_in; (void)out_size;
    const float* x   = (const float*)d_in[0];
    const float* h   = (const float*)d_in[1];
    const float* g   = (const float*)d_in[2];
    const float* Wx  = (const float*)d_in[3];
    const float* bx  = (const float*)d_in[4];
    const float* Wh  = (const float*)d_in[5];
    const float* bh  = (const float*)d_in[6];
    const float* Wgh = (const float*)d_in[7];
    const float* bgh = (const float*)d_in[8];
    const float* Whd = (const float*)d_in[9];
    const float* bhd = (const float*)d_in[10];
    const float* Wg  = (const float*)d_in[11];
    const float* bg  = (const float*)d_in[12];

    float* out  = (float*)d_out;
    float* hnew = out;
    float* gnew = out + (size_t)BDIM * HD;

    void *pS1, *pS2, *pHd;
    cudaGetSymbolAddress(&pS1, g_S1);
    cudaGetSymbolAddress(&pS2, g_S2);
    cudaGetSymbolAddress(&pHd, g_hd);

    cudaFuncSetAttribute(gemm_tf32_kernel, cudaFuncAttributeMaxDynamicSharedMemorySize,
                         SMEM_BYTES);

    const int H = HD;

    // Stage 1: S1 = [z | r | u | cand_x], ldc 8192
    {
        GArgs a;
        a.C = (float*)pS1; a.ldc = 8192;
        int nA[4] = {3, 3, 3, 1};
        const float* A[4][3] = {{x, h, g}, {x, h, g}, {x, h, g}, {x, x, x}};
        const float* W[4][3] = {{Wx, Wh, Wgh},
                                {Wx + H, Wh + H, Wgh + H},
                                {Wx + 3 * H, Wh + 2 * H, Wgh + 2 * H},
                                {Wx + 2 * H, Wx, Wx}};
        long long L[4][3] = {{4 * H, 3 * H, 3 * H},
                             {4 * H, 3 * H, 3 * H},
                             {4 * H, 3 * H, 3 * H},
                             {4 * H, 4 * H, 4 * H}};
        const float* Bp[4][3] = {{bx, bh, bgh},
                                 {bx + H, bh + H, bgh + H},
                                 {bx + 3 * H, bh + 2 * H, bgh + 2 * H},
                                 {bx + 2 * H, bx, bx}};
        for (int i = 0; i < 4; i++) {
            a.nA[i] = nA[i];
            for (int j = 0; j < 3; j++) {
                a.A[i][j] = A[i][j]; a.W[i][j] = W[i][j];
                a.ldw[i][j] = L[i][j]; a.bias[i][j] = Bp[i][j];
            }
        }
        gemm_tf32_kernel<<<dim3(64, 32), 256, SMEM_BYTES>>>(a);
    }

    unsigned epiBlocks = (unsigned)(((size_t)BDIM * HD / 4) / 256);
    epi1_kernel<<<epiBlocks, 256>>>(h, g, hnew);

    // Stage 2: S2 = [z2 | r2 | cand2], ldc 6144
    {
        GArgs a;
        a.C = (float*)pS2; a.ldc = 6144;
        const float* hd = (const float*)pHd;
        int nA[4] = {2, 2, 1, 1};
        const float* A[4][3] = {{hd, g, hd}, {hd, g, hd}, {hd, hd, hd}, {hd, hd, hd}};
        const float* W[4][3] = {{Whd, Wg, Whd},
                                {Whd + H, Wg + H, Whd},
                                {Whd + 2 * H, Whd, Whd},
                                {Whd, Whd, Whd}};
        long long L[4][3] = {{3 * H, 2 * H, 3 * H},
                             {3 * H, 2 * H, 3 * H},
                             {3 * H, 3 * H, 3 * H},
                             {3 * H, 3 * H, 3 * H}};
        const float* Bp[4][3] = {{bhd, bg, bhd},
                                 {bhd + H, bg + H, bhd},
                                 {bhd + 2 * H, bhd, bhd},
                                 {bhd, bhd, bhd}};
        for (int i = 0; i < 4; i++) {
            a.nA[i] = nA[i];
            for (int j = 0; j < 3; j++) {
                a.A[i][j] = A[i][j]; a.W[i][j] = W[i][j];
                a.ldw[i][j] = L[i][j]; a.bias[i][j] = Bp[i][j];
            }
        }
        gemm_tf32_kernel<<<dim3(64, 24), 256, SMEM_BYTES>>>(a);
    }

    epi2_kernel<<<epiBlocks, 256>>>(g, gnew);
}

// round 6
// speedup vs baseline: 1.6509x; 1.6509x over previous
#include <cuda_runtime.h>
#include <cuda_fp16.h>
#include <stdint.h>
#include <math.h>

#define HD   2048
#define BDIM 8192
#define BK   32
#define NST  4
#define A_WORDS 2048            // 128 rows * 16 words (word = 2 fp16)
#define B_WORDS 4096            // 256 rows * 16 words
#define SMEM_WORDS (NST * (A_WORDS + B_WORDS))
#define SMEM_BYTES (SMEM_WORDS * 4)   // 98304

// ---------------- device scratch ----------------
__device__ float  g_S1[(size_t)BDIM * 8192];    // [z | r | u | cand_x]
__device__ float  g_S2[(size_t)BDIM * 6144];    // [z2 | r2 | cand2]
__device__ __half g_x16[(size_t)BDIM * HD];
__device__ __half g_h16[(size_t)BDIM * HD];
__device__ __half g_g16[(size_t)BDIM * HD];
__device__ __half g_hd16[(size_t)BDIM * HD];
__device__ __half g_W16[(size_t)30720 * HD];    // all weights, transposed to [N][K]

// ---------------- PTX helpers ----------------
#define CP_ASYNC(dst, src) \
    asm volatile("cp.async.cg.shared.global [%0], [%1], 16;" :: "r"(dst), "l"(src))
#define CP_COMMIT() asm volatile("cp.async.commit_group;" ::: "memory")
#define CP_WAIT(n)  asm volatile("cp.async.wait_group %0;" :: "n"(n) : "memory")

__device__ __forceinline__ void mma16(float c[4], const uint32_t a[4], const uint32_t b[2]) {
    asm volatile(
        "mma.sync.aligned.m16n8k16.row.col.f32.f16.f16.f32 "
        "{%0,%1,%2,%3}, {%4,%5,%6,%7}, {%8,%9}, {%0,%1,%2,%3};\n"
        : "+f"(c[0]), "+f"(c[1]), "+f"(c[2]), "+f"(c[3])
        : "r"(a[0]), "r"(a[1]), "r"(a[2]), "r"(a[3]), "r"(b[0]), "r"(b[1]));
}

// swizzled word index for (row r, 16B-chunk ch, word-in-chunk wo); row = 16 words
__device__ __forceinline__ int swz(int r, int ch, int wo) {
    return r * 16 + ((ch ^ ((r >> 1) & 3)) << 2) + wo;
}

// ---------------- GEMM args ----------------
struct GArgs {
    float* C;
    long long ldc;
    int nA[4];
    const __half* A[4][3];     // fp16 activations [8192][2048]
    int wrow[4][3];            // absolute row offset into g_W16
    const float* bias[4][3];
};

// grid: x = M tiles (64), y = N tiles. blk = y>>3 (gate block), nloc = (y&7)*256
__global__ __launch_bounds__(256, 1)
void gemm_f16_kernel(const __grid_constant__ GArgs args, const __half* __restrict__ WB) {
    extern __shared__ uint32_t sm[];
    uint32_t* smA = sm;                       // [NST][A_WORDS]
    uint32_t* smB = sm + NST * A_WORDS;       // [NST][B_WORDS]

    const int tid  = threadIdx.x;
    const int lane = tid & 31;
    const int warp = tid >> 5;
    const int wm = warp & 1;     // 2 warps along M (64 rows)
    const int wn = warp >> 1;    // 4 warps along N (64 cols)

    const int m0   = blockIdx.x << 7;
    const int blk  = blockIdx.y >> 3;
    const int nloc = (blockIdx.y & 7) << 8;
    const int nA   = args.nA[blk];
    const int iters = nA << 6;                // nA * (2048/32)

    const __half* Ap[3];
    int wr[3];
#pragma unroll
    for (int a = 0; a < 3; a++) { Ap[a] = args.A[blk][a]; wr[a] = args.wrow[blk][a]; }

    float acc[4][8][4];
#pragma unroll
    for (int i = 0; i < 4; i++)
#pragma unroll
        for (int j = 0; j < 8; j++)
#pragma unroll
            for (int k = 0; k < 4; k++) acc[i][j][k] = 0.f;

    const int r4 = tid >> 2;     // 0..63
    const int ch = tid & 3;      // 16B chunk within 64B row

    auto load_stage = [&](int it) {
        const int s = it & (NST - 1);
        const int a = it >> 6;
        const int k0 = (it & 63) << 5;
        uint32_t* dA = smA + s * A_WORDS;
        uint32_t* dB = smB + s * B_WORDS;
        const __half* Ab = Ap[a];
#pragma unroll
        for (int i = 0; i < 2; i++) {
            const int r = r4 + (i << 6);
            uint32_t dst = (uint32_t)__cvta_generic_to_shared(dA + swz(r, ch, 0));
            CP_ASYNC(dst, Ab + (size_t)(m0 + r) * HD + k0 + ch * 8);
        }
        const size_t wbase = (size_t)(wr[a] + nloc) * HD + k0 + ch * 8;
#pragma unroll
        for (int i = 0; i < 4; i++) {
            const int r = r4 + (i << 6);
            uint32_t dst = (uint32_t)__cvta_generic_to_shared(dB + swz(r, ch, 0));
            CP_ASYNC(dst, WB + wbase + (size_t)r * HD);
        }
        CP_COMMIT();
    };

    const int tig = lane & 3;
    const int gid = lane >> 2;

    auto compute = [&](int s) {
        const uint32_t* cA = smA + s * A_WORDS;
        const uint32_t* cB = smB + s * B_WORDS;
#pragma unroll
        for (int ks = 0; ks < 2; ks++) {
            uint32_t af[4][4], bf[8][2];
            const int c0 = 2 * ks, c1 = 2 * ks + 1;
#pragma unroll
            for (int mt = 0; mt < 4; mt++) {
                const int r = wm * 64 + mt * 16 + gid;
                af[mt][0] = cA[swz(r, c0, tig)];
                af[mt][1] = cA[swz(r + 8, c0, tig)];
                af[mt][2] = cA[swz(r, c1, tig)];
                af[mt][3] = cA[swz(r + 8, c1, tig)];
            }
#pragma unroll
            for (int nt = 0; nt < 8; nt++) {
                const int n = wn * 64 + nt * 8 + gid;
                bf[nt][0] = cB[swz(n, c0, tig)];
                bf[nt][1] = cB[swz(n, c1, tig)];
            }
#pragma unroll
            for (int mt = 0; mt < 4; mt++)
#pragma unroll
                for (int nt = 0; nt < 8; nt++)
                    mma16(acc[mt][nt], af[mt], bf[nt]);
        }
    };

    load_stage(0);
    load_stage(1);
    load_stage(2);

#pragma unroll 1
    for (int it = 0; it < iters; it++) {
        CP_WAIT(2);
        __syncthreads();
        if (it + 3 < iters) load_stage(it + 3);
        else CP_COMMIT();   // dummy group keeps wait_group(2) semantics exact at tail
        compute(it & (NST - 1));
    }

    // epilogue: bias + store fp32
    const int cbase = blockIdx.y << 8;
#pragma unroll
    for (int nt = 0; nt < 8; nt++) {
        const int cl = wn * 64 + nt * 8 + 2 * tig;
        float bs0 = 0.f, bs1 = 0.f;
        for (int a = 0; a < nA; a++) {
            bs0 += args.bias[blk][a][nloc + cl];
            bs1 += args.bias[blk][a][nloc + cl + 1];
        }
#pragma unroll
        for (int mt = 0; mt < 4; mt++) {
            const int r = m0 + wm * 64 + mt * 16 + gid;
            float2 v0 = make_float2(acc[mt][nt][0] + bs0, acc[mt][nt][1] + bs1);
            float2 v1 = make_float2(acc[mt][nt][2] + bs0, acc[mt][nt][3] + bs1);
            *(float2*)(args.C + (size_t)r * args.ldc + cbase + cl) = v0;
            *(float2*)(args.C + (size_t)(r + 8) * args.ldc + cbase + cl) = v1;
        }
    }
}

// ---------------- prep: activations fp32 -> fp16 ----------------
__global__ void actconv_kernel(const float* __restrict__ x, const float* __restrict__ h,
                               const float* __restrict__ g) {
    const float* src = (blockIdx.y == 0) ? x : (blockIdx.y == 1) ? h : g;
    __half* dst = (blockIdx.y == 0) ? g_x16 : (blockIdx.y == 1) ? g_h16 : g_g16;
    size_t i = ((size_t)blockIdx.x * blockDim.x + threadIdx.x) * 4;
    float4 v = *(const float4*)(src + i);
    __half2* d = (__half2*)(dst + i);
    d[0] = __floats2half2_rn(v.x, v.y);
    d[1] = __floats2half2_rn(v.z, v.w);
}

// ---------------- prep: weights fp32 [K][N] -> fp16 [N][K] in g_W16 ----------------
struct TArgs {
    const float* W[5];
    int ldw[5];
    int ntiles[5];    // n-dim 32-tiles per matrix
    int outRow[5];    // row offset in g_W16
};
__global__ void wtrans_kernel(const __grid_constant__ TArgs ta) {
    __shared__ float t[32][33];
    int xt = blockIdx.x, m = 0;
    while (xt >= ta.ntiles[m]) { xt -= ta.ntiles[m]; m++; }
    const float* W = ta.W[m];
    const int ldw = ta.ldw[m];
    const int n0 = xt << 5, k0 = blockIdx.y << 5;
    const int tx = threadIdx.x, ty = threadIdx.y;
#pragma unroll
    for (int i = 0; i < 4; i++)
        t[ty + 8 * i][tx] = W[(size_t)(k0 + ty + 8 * i) * ldw + n0 + tx];
    __syncthreads();
#pragma unroll
    for (int i = 0; i < 4; i++)
        g_W16[(size_t)(ta.outRow[m] + n0 + ty + 8 * i) * HD + k0 + tx] =
            __float2half_rn(t[tx][ty + 8 * i]);
}

// ---------------- elementwise epilogues ----------------
__device__ __forceinline__ float sigm(float x) { return 1.f / (1.f + expf(-x)); }

__global__ void epi1_kernel(const float* __restrict__ h, const float* __restrict__ g,
                            float* __restrict__ hnew) {
    size_t e0 = ((size_t)blockIdx.x * blockDim.x + threadIdx.x) * 4;
    size_t b = e0 >> 11, j = e0 & 2047;
    const float* row = g_S1 + b * 8192 + j;
    float4 zp = *(const float4*)(row);
    float4 rp = *(const float4*)(row + 2048);
    float4 up = *(const float4*)(row + 4096);
    float4 cp = *(const float4*)(row + 6144);
    float4 hv = *(const float4*)(h + e0);
    float4 gv = *(const float4*)(g + e0);
    float4 hn, hd;
#define DO1(f)                                                     \
    {                                                              \
        float z = sigm(zp.f), r = sigm(rp.f), uu = sigm(up.f);     \
        float cand = tanhf(cp.f + r * hv.f + uu * gv.f);           \
        hn.f = (1.f - z) * hv.f + z * cand;                        \
        hd.f = hn.f - hv.f;                                        \
    }
    DO1(x) DO1(y) DO1(z) DO1(w)
#undef DO1
    *(float4*)(hnew + e0) = hn;
    __half2* hdp = (__half2*)(g_hd16 + e0);
    hdp[0] = __floats2half2_rn(hd.x, hd.y);
    hdp[1] = __floats2half2_rn(hd.z, hd.w);
}

__global__ void epi2_kernel(const float* __restrict__ g, float* __restrict__ gnew) {
    size_t e0 = ((size_t)blockIdx.x * blockDim.x + threadIdx.x) * 4;
    size_t b = e0 >> 11, j = e0 & 2047;
    const float* row = g_S2 + b * 6144 + j;
    float4 zp = *(const float4*)(row);
    float4 rp = *(const float4*)(row + 2048);
    float4 cp = *(const float4*)(row + 4096);
    float4 gv = *(const float4*)(g + e0);
    float4 gn;
#define DO2(f)                                       \
    {                                                \
        float z = sigm(zp.f), r = sigm(rp.f);        \
        float cand = tanhf(cp.f + r * gv.f);         \
        gn.f = (1.f - z) * gv.f + z * cand;          \
    }
    DO2(x) DO2(y) DO2(z) DO2(w)
#undef DO2
    *(float4*)(gnew + e0) = gn;
}

// ---------------- host ----------------
extern "C" void kernel_launch(void* const* d_in, const int* in_sizes, int n_in,
                              void* d_out, int out_size) {
    (void)in_sizes; (void)n_in; (void)out_size;
    const float* x   = (const float*)d_in[0];
    const float* h   = (const float*)d_in[1];
    const float* g   = (const float*)d_in[2];
    const float* Wx  = (const float*)d_in[3];
    const float* bx  = (const float*)d_in[4];
    const float* Wh  = (const float*)d_in[5];
    const float* bh  = (const float*)d_in[6];
    const float* Wgh = (const float*)d_in[7];
    const float* bgh = (const float*)d_in[8];
    const float* Whd = (const float*)d_in[9];
    const float* bhd = (const float*)d_in[10];
    const float* Wg  = (const float*)d_in[11];
    const float* bg  = (const float*)d_in[12];

    float* out  = (float*)d_out;
    float* hnew = out;
    float* gnew = out + (size_t)BDIM * HD;

    void *pS1, *pS2, *pX, *pH, *pG, *pHd, *pW;
    cudaGetSymbolAddress(&pS1, g_S1);
    cudaGetSymbolAddress(&pS2, g_S2);
    cudaGetSymbolAddress(&pX, g_x16);
    cudaGetSymbolAddress(&pH, g_h16);
    cudaGetSymbolAddress(&pG, g_g16);
    cudaGetSymbolAddress(&pHd, g_hd16);
    cudaGetSymbolAddress(&pW, g_W16);

    cudaFuncSetAttribute(gemm_f16_kernel, cudaFuncAttributeMaxDynamicSharedMemorySize,
                         SMEM_BYTES);

    const int H = HD;
    // g_W16 row layout: Wx^T rows [0,8192), Wh^T [8192,14336), Wgh^T [14336,20480),
    //                   Whd^T [20480,26624), Wg^T [26624,30720)
    const int RWx = 0, RWh = 8192, RWgh = 14336, RWhd = 20480, RWg = 26624;

    // 1) activations -> fp16
    actconv_kernel<<<dim3((unsigned)((size_t)BDIM * HD / 4 / 256), 3), 256>>>(x, h, g);

    // 2) weights -> transposed fp16
    {
        TArgs ta;
        const float* Ws[5] = {Wx, Wh, Wgh, Whd, Wg};
        int lds[5] = {4 * H, 3 * H, 3 * H, 3 * H, 2 * H};
        int nts[5] = {256, 192, 192, 192, 128};   // ncols/32
        int orow[5] = {RWx, RWh, RWgh, RWhd, RWg};
        for (int i = 0; i < 5; i++) {
            ta.W[i] = Ws[i]; ta.ldw[i] = lds[i]; ta.ntiles[i] = nts[i]; ta.outRow[i] = orow[i];
        }
        wtrans_kernel<<<dim3(960, 64), dim3(32, 8)>>>(ta);
    }

    // 3) stage-1 GEMM: S1 = [z | r | u | cand_x], ldc 8192
    {
        GArgs a;
        a.C = (float*)pS1; a.ldc = 8192;
        const __half* x16 = (const __half*)pX;
        const __half* h16 = (const __half*)pH;
        const __half* g16 = (const __half*)pG;
        int nA[4] = {3, 3, 3, 1};
        const __half* A[4][3] = {{x16, h16, g16}, {x16, h16, g16}, {x16, h16, g16},
                                 {x16, x16, x16}};
        int WR[4][3] = {{RWx, RWh, RWgh},
                        {RWx + H, RWh + H, RWgh + H},
                        {RWx + 3 * H, RWh + 2 * H, RWgh + 2 * H},
                        {RWx + 2 * H, 0, 0}};
        const float* Bp[4][3] = {{bx, bh, bgh},
                                 {bx + H, bh + H, bgh + H},
                                 {bx + 3 * H, bh + 2 * H, bgh + 2 * H},
                                 {bx + 2 * H, bx, bx}};
        for (int i = 0; i < 4; i++) {
            a.nA[i] = nA[i];
            for (int j = 0; j < 3; j++) {
                a.A[i][j] = A[i][j]; a.wrow[i][j] = WR[i][j]; a.bias[i][j] = Bp[i][j];
            }
        }
        gemm_f16_kernel<<<dim3(64, 32), 256, SMEM_BYTES>>>(a, (const __half*)pW);
    }

    unsigned epiBlocks = (unsigned)(((size_t)BDIM * HD / 4) / 256);
    epi1_kernel<<<epiBlocks, 256>>>(h, g, hnew);

    // 4) stage-2 GEMM: S2 = [z2 | r2 | cand2], ldc 6144
    {
        GArgs a;
        a.C = (float*)pS2; a.ldc = 6144;
        const __half* hd16 = (const __half*)pHd;
        const __half* g16 = (const __half*)pG;
        int nA[4] = {2, 2, 1, 1};
        const __half* A[4][3] = {{hd16, g16, hd16}, {hd16, g16, hd16},
                                 {hd16, hd16, hd16}, {hd16, hd16, hd16}};
        int WR[4][3] = {{RWhd, RWg, 0},
                        {RWhd + H, RWg + H, 0},
                        {RWhd + 2 * H, 0, 0},
                        {0, 0, 0}};
        const float* Bp[4][3] = {{bhd, bg, bhd},
                                 {bhd + H, bg + H, bhd},
                                 {bhd + 2 * H, bhd, bhd},
                                 {bhd, bhd, bhd}};
        for (int i = 0; i < 4; i++) {
            a.nA[i] = nA[i];
            for (int j = 0; j < 3; j++) {
                a.A[i][j] = A[i][j]; a.wrow[i][j] = WR[i][j]; a.bias[i][j] = Bp[i][j];
            }
        }
        gemm_f16_kernel<<<dim3(64, 24), 256, SMEM_BYTES>>>(a, (const __half*)pW);
    }

    epi2_kernel<<<epiBlocks, 256>>>(g, gnew);
}

// round 7
// speedup vs baseline: 1.7323x; 1.0493x over previous
#include <cuda_runtime.h>
#include <cuda_fp16.h>
#include <stdint.h>
#include <math.h>

#define HD   2048
#define BDIM 8192
#define BK   32
#define NST  4
#define A_WORDS 2048            // 128 rows * 16 words (word = 2 fp16)
#define B_WORDS 4096            // 256 rows * 16 words
#define SMEM_WORDS (NST * (A_WORDS + B_WORDS))
#define SMEM_BYTES (SMEM_WORDS * 4)   // 98304

// ---------------- device scratch ----------------
__device__ float  g_S1[(size_t)BDIM * 8192];    // [z | r | u | cand_x]
__device__ float  g_S2[(size_t)BDIM * 6144];    // [z2 | r2 | cand2]
__device__ __half g_x16[(size_t)BDIM * HD];
__device__ __half g_h16[(size_t)BDIM * HD];
__device__ __half g_g16[(size_t)BDIM * HD];
__device__ __half g_hd16[(size_t)BDIM * HD];
__device__ __half g_W16[(size_t)30720 * HD];    // all weights, transposed to [N][K]

// ---------------- PTX helpers ----------------
#define CP_ASYNC(dst, src) \
    asm volatile("cp.async.cg.shared.global [%0], [%1], 16;" :: "r"(dst), "l"(src))
#define CP_COMMIT() asm volatile("cp.async.commit_group;" ::: "memory")
#define CP_WAIT(n)  asm volatile("cp.async.wait_group %0;" :: "n"(n) : "memory")

#define LDMX4(r0, r1, r2, r3, addr)                                            \
    asm volatile("ldmatrix.sync.aligned.m8n8.x4.shared.b16 {%0,%1,%2,%3}, [%4];" \
                 : "=r"(r0), "=r"(r1), "=r"(r2), "=r"(r3) : "r"(addr))

__device__ __forceinline__ void mma16(float c[4], const uint32_t a[4], const uint32_t b[2]) {
    asm volatile(
        "mma.sync.aligned.m16n8k16.row.col.f32.f16.f16.f32 "
        "{%0,%1,%2,%3}, {%4,%5,%6,%7}, {%8,%9}, {%0,%1,%2,%3};\n"
        : "+f"(c[0]), "+f"(c[1]), "+f"(c[2]), "+f"(c[3])
        : "r"(a[0]), "r"(a[1]), "r"(a[2]), "r"(a[3]), "r"(b[0]), "r"(b[1]));
}

// swizzled word index for (row r, 16B-chunk ch, word-in-chunk wo); row = 16 words
__device__ __forceinline__ int swz(int r, int ch, int wo) {
    return r * 16 + ((ch ^ ((r >> 1) & 3)) << 2) + wo;
}

// ---------------- GEMM args ----------------
struct GArgs {
    float* C;
    long long ldc;
    int nA[4];
    const __half* A[4][3];     // fp16 activations [8192][2048]
    int wrow[4][3];            // absolute row offset into g_W16
    const float* bias[4][3];
};

// grid: x = M tiles (64), y = N tiles. blk = y>>3 (gate block), nloc = (y&7)*256
__global__ __launch_bounds__(256, 1)
void gemm_f16_kernel(const __grid_constant__ GArgs args, const __half* __restrict__ WB) {
    extern __shared__ uint32_t sm[];
    uint32_t* smA = sm;                       // [NST][A_WORDS]
    uint32_t* smB = sm + NST * A_WORDS;       // [NST][B_WORDS]
    const uint32_t smA0 = (uint32_t)__cvta_generic_to_shared(smA);
    const uint32_t smB0 = (uint32_t)__cvta_generic_to_shared(smB);

    const int tid  = threadIdx.x;
    const int lane = tid & 31;
    const int warp = tid >> 5;
    const int wm = warp & 1;     // 2 warps along M (64 rows)
    const int wn = warp >> 1;    // 4 warps along N (64 cols)

    const int m0   = blockIdx.x << 7;
    const int blk  = blockIdx.y >> 3;
    const int nloc = (blockIdx.y & 7) << 8;
    const int nA   = args.nA[blk];
    const int iters = nA << 6;                // nA * (2048/32)

    const __half* Ap[3];
    int wr[3];
#pragma unroll
    for (int a = 0; a < 3; a++) { Ap[a] = args.A[blk][a]; wr[a] = args.wrow[blk][a]; }

    float acc[4][8][4];
#pragma unroll
    for (int i = 0; i < 4; i++)
#pragma unroll
        for (int j = 0; j < 8; j++)
#pragma unroll
            for (int k = 0; k < 4; k++) acc[i][j][k] = 0.f;

    const int r4 = tid >> 2;     // 0..63
    const int ch = tid & 3;      // 16B chunk within 64B row

    auto load_stage = [&](int it) {
        const int s = it & (NST - 1);
        const int a = it >> 6;
        const int k0 = (it & 63) << 5;
        uint32_t* dA = smA + s * A_WORDS;
        uint32_t* dB = smB + s * B_WORDS;
        const __half* Ab = Ap[a];
#pragma unroll
        for (int i = 0; i < 2; i++) {
            const int r = r4 + (i << 6);
            uint32_t dst = (uint32_t)__cvta_generic_to_shared(dA + swz(r, ch, 0));
            CP_ASYNC(dst, Ab + (size_t)(m0 + r) * HD + k0 + ch * 8);
        }
        const size_t wbase = (size_t)(wr[a] + nloc) * HD + k0 + ch * 8;
#pragma unroll
        for (int i = 0; i < 4; i++) {
            const int r = r4 + (i << 6);
            uint32_t dst = (uint32_t)__cvta_generic_to_shared(dB + swz(r, ch, 0));
            CP_ASYNC(dst, WB + wbase + (size_t)r * HD);
        }
        CP_COMMIT();
    };

    // ldmatrix per-lane geometry (constant across iterations)
    const int arow = wm * 64 + (lane & 15);      // + mt*16
    const int acsel = lane >> 4;                 // 0: k-lo chunk, 1: k-hi
    const int bnrow = wn * 64 + ((lane & 16) >> 1) + (lane & 7);  // + np*16
    const int bcsel = (lane >> 3) & 1;

    auto compute = [&](int s) {
        const uint32_t a_base = smA0 + (s * A_WORDS) * 4;
        const uint32_t b_base = smB0 + (s * B_WORDS) * 4;
#pragma unroll
        for (int ks = 0; ks < 2; ks++) {
            uint32_t af[4][4], bf[8][2];
#pragma unroll
            for (int mt = 0; mt < 4; mt++) {
                const int r = arow + mt * 16;
                const int c = (2 * ks + acsel) ^ ((r >> 1) & 3);
                const uint32_t addr = a_base + (r * 16 + (c << 2)) * 4;
                LDMX4(af[mt][0], af[mt][1], af[mt][2], af[mt][3], addr);
            }
#pragma unroll
            for (int np = 0; np < 4; np++) {
                const int n = bnrow + np * 16;
                const int c = (2 * ks + bcsel) ^ ((n >> 1) & 3);
                const uint32_t addr = b_base + (n * 16 + (c << 2)) * 4;
                LDMX4(bf[2 * np][0], bf[2 * np][1], bf[2 * np + 1][0], bf[2 * np + 1][1],
                      addr);
            }
#pragma unroll
            for (int mt = 0; mt < 4; mt++)
#pragma unroll
                for (int nt = 0; nt < 8; nt++)
                    mma16(acc[mt][nt], af[mt], bf[nt]);
        }
    };

    load_stage(0);
    load_stage(1);
    load_stage(2);

#pragma unroll 1
    for (int it = 0; it < iters; it++) {
        CP_WAIT(2);
        __syncthreads();
        if (it + 3 < iters) load_stage(it + 3);
        else CP_COMMIT();   // dummy group keeps wait_group(2) semantics exact at tail
        compute(it & (NST - 1));
    }

    // epilogue: bias + store fp32
    const int tig = lane & 3;
    const int gid = lane >> 2;
    const int cbase = blockIdx.y << 8;
#pragma unroll
    for (int nt = 0; nt < 8; nt++) {
        const int cl = wn * 64 + nt * 8 + 2 * tig;
        float bs0 = 0.f, bs1 = 0.f;
        for (int a = 0; a < nA; a++) {
            bs0 += args.bias[blk][a][nloc + cl];
            bs1 += args.bias[blk][a][nloc + cl + 1];
        }
#pragma unroll
        for (int mt = 0; mt < 4; mt++) {
            const int r = m0 + wm * 64 + mt * 16 + gid;
            float2 v0 = make_float2(acc[mt][nt][0] + bs0, acc[mt][nt][1] + bs1);
            float2 v1 = make_float2(acc[mt][nt][2] + bs0, acc[mt][nt][3] + bs1);
            *(float2*)(args.C + (size_t)r * args.ldc + cbase + cl) = v0;
            *(float2*)(args.C + (size_t)(r + 8) * args.ldc + cbase + cl) = v1;
        }
    }
}

// ---------------- prep: activations fp32 -> fp16 ----------------
__global__ void actconv_kernel(const float* __restrict__ x, const float* __restrict__ h,
                               const float* __restrict__ g) {
    const float* src = (blockIdx.y == 0) ? x : (blockIdx.y == 1) ? h : g;
    __half* dst = (blockIdx.y == 0) ? g_x16 : (blockIdx.y == 1) ? g_h16 : g_g16;
    size_t i = ((size_t)blockIdx.x * blockDim.x + threadIdx.x) * 4;
    float4 v = *(const float4*)(src + i);
    __half2* d = (__half2*)(dst + i);
    d[0] = __floats2half2_rn(v.x, v.y);
    d[1] = __floats2half2_rn(v.z, v.w);
}

// ---------------- prep: weights fp32 [K][N] -> fp16 [N][K] in g_W16 ----------------
struct TArgs {
    const float* W[5];
    int ldw[5];
    int ntiles[5];    // n-dim 32-tiles per matrix
    int outRow[5];    // row offset in g_W16
};
__global__ void wtrans_kernel(const __grid_constant__ TArgs ta) {
    __shared__ float t[32][33];
    int xt = blockIdx.x, m = 0;
    while (xt >= ta.ntiles[m]) { xt -= ta.ntiles[m]; m++; }
    const float* W = ta.W[m];
    const int ldw = ta.ldw[m];
    const int n0 = xt << 5, k0 = blockIdx.y << 5;
    const int tx = threadIdx.x, ty = threadIdx.y;
#pragma unroll
    for (int i = 0; i < 4; i++)
        t[ty + 8 * i][tx] = W[(size_t)(k0 + ty + 8 * i) * ldw + n0 + tx];
    __syncthreads();
#pragma unroll
    for (int i = 0; i < 4; i++)
        g_W16[(size_t)(ta.outRow[m] + n0 + ty + 8 * i) * HD + k0 + tx] =
            __float2half_rn(t[tx][ty + 8 * i]);
}

// ---------------- elementwise epilogues ----------------
__device__ __forceinline__ float sigm(float x) { return 1.f / (1.f + expf(-x)); }

__global__ void epi1_kernel(const float* __restrict__ h, const float* __restrict__ g,
                            float* __restrict__ hnew) {
    size_t e0 = ((size_t)blockIdx.x * blockDim.x + threadIdx.x) * 4;
    size_t b = e0 >> 11, j = e0 & 2047;
    const float* row = g_S1 + b * 8192 + j;
    float4 zp = *(const float4*)(row);
    float4 rp = *(const float4*)(row + 2048);
    float4 up = *(const float4*)(row + 4096);
    float4 cp = *(const float4*)(row + 6144);
    float4 hv = *(const float4*)(h + e0);
    float4 gv = *(const float4*)(g + e0);
    float4 hn, hd;
#define DO1(f)                                                     \
    {                                                              \
        float z = sigm(zp.f), r = sigm(rp.f), uu = sigm(up.f);     \
        float cand = tanhf(cp.f + r * hv.f + uu * gv.f);           \
        hn.f = (1.f - z) * hv.f + z * cand;                        \
        hd.f = hn.f - hv.f;                                        \
    }
    DO1(x) DO1(y) DO1(z) DO1(w)
#undef DO1
    *(float4*)(hnew + e0) = hn;
    __half2* hdp = (__half2*)(g_hd16 + e0);
    hdp[0] = __floats2half2_rn(hd.x, hd.y);
    hdp[1] = __floats2half2_rn(hd.z, hd.w);
}

__global__ void epi2_kernel(const float* __restrict__ g, float* __restrict__ gnew) {
    size_t e0 = ((size_t)blockIdx.x * blockDim.x + threadIdx.x) * 4;
    size_t b = e0 >> 11, j = e0 & 2047;
    const float* row = g_S2 + b * 6144 + j;
    float4 zp = *(const float4*)(row);
    float4 rp = *(const float4*)(row + 2048);
    float4 cp = *(const float4*)(row + 4096);
    float4 gv = *(const float4*)(g + e0);
    float4 gn;
#define DO2(f)                                       \
    {                                                \
        float z = sigm(zp.f), r = sigm(rp.f);        \
        float cand = tanhf(cp.f + r * gv.f);         \
        gn.f = (1.f - z) * gv.f + z * cand;          \
    }
    DO2(x) DO2(y) DO2(z) DO2(w)
#undef DO2
    *(float4*)(gnew + e0) = gn;
}

// ---------------- host ----------------
extern "C" void kernel_launch(void* const* d_in, const int* in_sizes, int n_in,
                              void* d_out, int out_size) {
    (void)in_sizes; (void)n_in; (void)out_size;
    const float* x   = (const float*)d_in[0];
    const float* h   = (const float*)d_in[1];
    const float* g   = (const float*)d_in[2];
    const float* Wx  = (const float*)d_in[3];
    const float* bx  = (const float*)d_in[4];
    const float* Wh  = (const float*)d_in[5];
    const float* bh  = (const float*)d_in[6];
    const float* Wgh = (const float*)d_in[7];
    const float* bgh = (const float*)d_in[8];
    const float* Whd = (const float*)d_in[9];
    const float* bhd = (const float*)d_in[10];
    const float* Wg  = (const float*)d_in[11];
    const float* bg  = (const float*)d_in[12];

    float* out  = (float*)d_out;
    float* hnew = out;
    float* gnew = out + (size_t)BDIM * HD;

    void *pS1, *pS2, *pX, *pH, *pG, *pHd, *pW;
    cudaGetSymbolAddress(&pS1, g_S1);
    cudaGetSymbolAddress(&pS2, g_S2);
    cudaGetSymbolAddress(&pX, g_x16);
    cudaGetSymbolAddress(&pH, g_h16);
    cudaGetSymbolAddress(&pG, g_g16);
    cudaGetSymbolAddress(&pHd, g_hd16);
    cudaGetSymbolAddress(&pW, g_W16);

    cudaFuncSetAttribute(gemm_f16_kernel, cudaFuncAttributeMaxDynamicSharedMemorySize,
                         SMEM_BYTES);

    const int H = HD;
    const int RWx = 0, RWh = 8192, RWgh = 14336, RWhd = 20480, RWg = 26624;

    // 1) activations -> fp16
    actconv_kernel<<<dim3((unsigned)((size_t)BDIM * HD / 4 / 256), 3), 256>>>(x, h, g);

    // 2) weights -> transposed fp16
    {
        TArgs ta;
        const float* Ws[5] = {Wx, Wh, Wgh, Whd, Wg};
        int lds[5] = {4 * H, 3 * H, 3 * H, 3 * H, 2 * H};
        int nts[5] = {256, 192, 192, 192, 128};
        int orow[5] = {RWx, RWh, RWgh, RWhd, RWg};
        for (int i = 0; i < 5; i++) {
            ta.W[i] = Ws[i]; ta.ldw[i] = lds[i]; ta.ntiles[i] = nts[i]; ta.outRow[i] = orow[i];
        }
        wtrans_kernel<<<dim3(960, 64), dim3(32, 8)>>>(ta);
    }

    // 3) stage-1 GEMM: S1 = [z | r | u | cand_x], ldc 8192
    {
        GArgs a;
        a.C = (float*)pS1; a.ldc = 8192;
        const __half* x16 = (const __half*)pX;
        const __half* h16 = (const __half*)pH;
        const __half* g16 = (const __half*)pG;
        int nA[4] = {3, 3, 3, 1};
        const __half* A[4][3] = {{x16, h16, g16}, {x16, h16, g16}, {x16, h16, g16},
                                 {x16, x16, x16}};
        int WR[4][3] = {{RWx, RWh, RWgh},
                        {RWx + H, RWh + H, RWgh + H},
                        {RWx + 3 * H, RWh + 2 * H, RWgh + 2 * H},
                        {RWx + 2 * H, 0, 0}};
        const float* Bp[4][3] = {{bx, bh, bgh},
                                 {bx + H, bh + H, bgh + H},
                                 {bx + 3 * H, bh + 2 * H, bgh + 2 * H},
                                 {bx + 2 * H, bx, bx}};
        for (int i = 0; i < 4; i++) {
            a.nA[i] = nA[i];
            for (int j = 0; j < 3; j++) {
                a.A[i][j] = A[i][j]; a.wrow[i][j] = WR[i][j]; a.bias[i][j] = Bp[i][j];
            }
        }
        gemm_f16_kernel<<<dim3(64, 32), 256, SMEM_BYTES>>>(a, (const __half*)pW);
    }

    unsigned epiBlocks = (unsigned)(((size_t)BDIM * HD / 4) / 256);
    epi1_kernel<<<epiBlocks, 256>>>(h, g, hnew);

    // 4) stage-2 GEMM: S2 = [z2 | r2 | cand2], ldc 6144
    {
        GArgs a;
        a.C = (float*)pS2; a.ldc = 6144;
        const __half* hd16 = (const __half*)pHd;
        const __half* g16 = (const __half*)pG;
        int nA[4] = {2, 2, 1, 1};
        const __half* A[4][3] = {{hd16, g16, hd16}, {hd16, g16, hd16},
                                 {hd16, hd16, hd16}, {hd16, hd16, hd16}};
        int WR[4][3] = {{RWhd, RWg, 0},
                        {RWhd + H, RWg + H, 0},
                        {RWhd + 2 * H, 0, 0},
                        {0, 0, 0}};
        const float* Bp[4][3] = {{bhd, bg, bhd},
                                 {bhd + H, bg + H, bhd},
                                 {bhd + 2 * H, bhd, bhd},
                                 {bhd, bhd, bhd}};
        for (int i = 0; i < 4; i++) {
            a.nA[i] = nA[i];
            for (int j = 0; j < 3; j++) {
                a.A[i][j] = A[i][j]; a.wrow[i][j] = WR[i][j]; a.bias[i][j] = Bp[i][j];
            }
        }
        gemm_f16_kernel<<<dim3(64, 24), 256, SMEM_BYTES>>>(a, (const __half*)pW);
    }

    epi2_kernel<<<epiBlocks, 256>>>(g, gnew);
}

// round 8
// speedup vs baseline: 2.0681x; 1.1938x over previous
#include <cuda_runtime.h>
#include <cuda_fp16.h>
#include <stdint.h>
#include <math.h>

#define HD   2048
#define BDIM 8192
#define BK   32
#define NST  4
#define A_WORDS 2048            // 128 rows * 16 words (word = 2 fp16)
#define B_WORDS 2048            // 128 rows * 16 words
#define SMEM_WORDS (NST * (A_WORDS + B_WORDS))
#define SMEM_BYTES (SMEM_WORDS * 4)   // 65536

// ---------------- device scratch ----------------
__device__ float  g_S1[(size_t)BDIM * 8192];    // [z | r | u | cand_x]
__device__ float  g_S2[(size_t)BDIM * 6144];    // [z2 | r2 | cand2]
__device__ __half g_x16[(size_t)BDIM * HD];
__device__ __half g_h16[(size_t)BDIM * HD];
__device__ __half g_g16[(size_t)BDIM * HD];
__device__ __half g_hd16[(size_t)BDIM * HD];
__device__ __half g_W16[(size_t)30720 * HD];    // all weights, transposed to [N][K]

// ---------------- PTX helpers ----------------
#define CP_ASYNC(dst, src) \
    asm volatile("cp.async.cg.shared.global [%0], [%1], 16;" :: "r"(dst), "l"(src))
#define CP_COMMIT() asm volatile("cp.async.commit_group;" ::: "memory")
#define CP_WAIT(n)  asm volatile("cp.async.wait_group %0;" :: "n"(n) : "memory")

#define LDMX4(r0, r1, r2, r3, addr)                                            \
    asm volatile("ldmatrix.sync.aligned.m8n8.x4.shared.b16 {%0,%1,%2,%3}, [%4];" \
                 : "=r"(r0), "=r"(r1), "=r"(r2), "=r"(r3) : "r"(addr))

__device__ __forceinline__ void mma16(float c[4], const uint32_t a[4], const uint32_t b[2]) {
    asm volatile(
        "mma.sync.aligned.m16n8k16.row.col.f32.f16.f16.f32 "
        "{%0,%1,%2,%3}, {%4,%5,%6,%7}, {%8,%9}, {%0,%1,%2,%3};\n"
        : "+f"(c[0]), "+f"(c[1]), "+f"(c[2]), "+f"(c[3])
        : "r"(a[0]), "r"(a[1]), "r"(a[2]), "r"(a[3]), "r"(b[0]), "r"(b[1]));
}

// swizzled word index for (row r, 16B-chunk ch, word-in-chunk wo); row = 16 words
__device__ __forceinline__ int swz(int r, int ch, int wo) {
    return r * 16 + ((ch ^ ((r >> 1) & 3)) << 2) + wo;
}

// ---------------- GEMM args ----------------
struct GArgs {
    float* C;
    long long ldc;
    int nA[4];
    const __half* A[4][3];     // fp16 activations [8192][2048]
    int wrow[4][3];            // absolute row offset into g_W16
    const float* bias[4][3];
};

// grid: x = M tiles (64), y = N tiles. blk = y>>4 (gate block), nloc = (y&15)*128
__global__ __launch_bounds__(256, 2)
void gemm_f16_kernel(const __grid_constant__ GArgs args, const __half* __restrict__ WB) {
    extern __shared__ uint32_t sm[];
    uint32_t* smA = sm;                       // [NST][A_WORDS]
    uint32_t* smB = sm + NST * A_WORDS;       // [NST][B_WORDS]
    const uint32_t smA0 = (uint32_t)__cvta_generic_to_shared(smA);
    const uint32_t smB0 = (uint32_t)__cvta_generic_to_shared(smB);

    const int tid  = threadIdx.x;
    const int lane = tid & 31;
    const int warp = tid >> 5;
    const int wm = warp & 1;     // 2 warps along M (64 rows)
    const int wn = warp >> 1;    // 4 warps along N (32 cols)

    const int m0   = blockIdx.x << 7;
    const int blk  = blockIdx.y >> 4;
    const int nloc = (blockIdx.y & 15) << 7;
    const int nA   = args.nA[blk];
    const int iters = nA << 6;                // nA * (2048/32)

    const __half* Ap[3];
    int wr[3];
#pragma unroll
    for (int a = 0; a < 3; a++) { Ap[a] = args.A[blk][a]; wr[a] = args.wrow[blk][a]; }

    float acc[4][4][4];
#pragma unroll
    for (int i = 0; i < 4; i++)
#pragma unroll
        for (int j = 0; j < 4; j++)
#pragma unroll
            for (int k = 0; k < 4; k++) acc[i][j][k] = 0.f;

    const int r4 = tid >> 2;     // 0..63
    const int ch = tid & 3;      // 16B chunk within 64B row

    auto load_stage = [&](int it) {
        const int s = it & (NST - 1);
        const int a = it >> 6;
        const int k0 = (it & 63) << 5;
        uint32_t* dA = smA + s * A_WORDS;
        uint32_t* dB = smB + s * B_WORDS;
        const __half* Ab = Ap[a];
#pragma unroll
        for (int i = 0; i < 2; i++) {
            const int r = r4 + (i << 6);
            uint32_t dst = (uint32_t)__cvta_generic_to_shared(dA + swz(r, ch, 0));
            CP_ASYNC(dst, Ab + (size_t)(m0 + r) * HD + k0 + ch * 8);
        }
        const size_t wbase = (size_t)(wr[a] + nloc) * HD + k0 + ch * 8;
#pragma unroll
        for (int i = 0; i < 2; i++) {
            const int r = r4 + (i << 6);
            uint32_t dst = (uint32_t)__cvta_generic_to_shared(dB + swz(r, ch, 0));
            CP_ASYNC(dst, WB + wbase + (size_t)r * HD);
        }
        CP_COMMIT();
    };

    // ldmatrix per-lane geometry (constant across iterations)
    const int arow = wm * 64 + (lane & 15);      // + mt*16
    const int acsel = lane >> 4;                 // 0: k-lo chunk, 1: k-hi
    const int bnrow = wn * 32 + ((lane & 16) >> 1) + (lane & 7);  // + np*16
    const int bcsel = (lane >> 3) & 1;

    auto compute = [&](int s) {
        const uint32_t a_base = smA0 + (s * A_WORDS) * 4;
        const uint32_t b_base = smB0 + (s * B_WORDS) * 4;
#pragma unroll
        for (int ks = 0; ks < 2; ks++) {
            uint32_t af[4][4], bf[4][2];
#pragma unroll
            for (int mt = 0; mt < 4; mt++) {
                const int r = arow + mt * 16;
                const int c = (2 * ks + acsel) ^ ((r >> 1) & 3);
                const uint32_t addr = a_base + (r * 16 + (c << 2)) * 4;
                LDMX4(af[mt][0], af[mt][1], af[mt][2], af[mt][3], addr);
            }
#pragma unroll
            for (int np = 0; np < 2; np++) {
                const int n = bnrow + np * 16;
                const int c = (2 * ks + bcsel) ^ ((n >> 1) & 3);
                const uint32_t addr = b_base + (n * 16 + (c << 2)) * 4;
                LDMX4(bf[2 * np][0], bf[2 * np][1], bf[2 * np + 1][0], bf[2 * np + 1][1],
                      addr);
            }
#pragma unroll
            for (int mt = 0; mt < 4; mt++)
#pragma unroll
                for (int nt = 0; nt < 4; nt++)
                    mma16(acc[mt][nt], af[mt], bf[nt]);
        }
    };

    load_stage(0);
    load_stage(1);
    load_stage(2);

#pragma unroll 1
    for (int it = 0; it < iters; it++) {
        CP_WAIT(2);
        __syncthreads();
        if (it + 3 < iters) load_stage(it + 3);
        else CP_COMMIT();   // dummy group keeps wait_group(2) semantics exact at tail
        compute(it & (NST - 1));
    }

    // epilogue: bias + store fp32
    const int tig = lane & 3;
    const int gid = lane >> 2;
    const int cbase = blockIdx.y << 7;
#pragma unroll
    for (int nt = 0; nt < 4; nt++) {
        const int cl = wn * 32 + nt * 8 + 2 * tig;
        float bs0 = 0.f, bs1 = 0.f;
        for (int a = 0; a < nA; a++) {
            bs0 += args.bias[blk][a][nloc + cl];
            bs1 += args.bias[blk][a][nloc + cl + 1];
        }
#pragma unroll
        for (int mt = 0; mt < 4; mt++) {
            const int r = m0 + wm * 64 + mt * 16 + gid;
            float2 v0 = make_float2(acc[mt][nt][0] + bs0, acc[mt][nt][1] + bs1);
            float2 v1 = make_float2(acc[mt][nt][2] + bs0, acc[mt][nt][3] + bs1);
            *(float2*)(args.C + (size_t)r * args.ldc + cbase + cl) = v0;
            *(float2*)(args.C + (size_t)(r + 8) * args.ldc + cbase + cl) = v1;
        }
    }
}

// ---------------- prep: activations fp32 -> fp16 ----------------
__global__ void actconv_kernel(const float* __restrict__ x, const float* __restrict__ h,
                               const float* __restrict__ g) {
    const float* src = (blockIdx.y == 0) ? x : (blockIdx.y == 1) ? h : g;
    __half* dst = (blockIdx.y == 0) ? g_x16 : (blockIdx.y == 1) ? g_h16 : g_g16;
    size_t i = ((size_t)blockIdx.x * blockDim.x + threadIdx.x) * 4;
    float4 v = *(const float4*)(src + i);
    __half2* d = (__half2*)(dst + i);
    d[0] = __floats2half2_rn(v.x, v.y);
    d[1] = __floats2half2_rn(v.z, v.w);
}

// ---------------- prep: weights fp32 [K][N] -> fp16 [N][K] in g_W16 ----------------
struct TArgs {
    const float* W[5];
    int ldw[5];
    int ntiles[5];    // n-dim 32-tiles per matrix
    int outRow[5];    // row offset in g_W16
};
__global__ void wtrans_kernel(const __grid_constant__ TArgs ta) {
    __shared__ float t[32][33];
    int xt = blockIdx.x, m = 0;
    while (xt >= ta.ntiles[m]) { xt -= ta.ntiles[m]; m++; }
    const float* W = ta.W[m];
    const int ldw = ta.ldw[m];
    const int n0 = xt << 5, k0 = blockIdx.y << 5;
    const int tx = threadIdx.x, ty = threadIdx.y;
#pragma unroll
    for (int i = 0; i < 4; i++)
        t[ty + 8 * i][tx] = W[(size_t)(k0 + ty + 8 * i) * ldw + n0 + tx];
    __syncthreads();
#pragma unroll
    for (int i = 0; i < 4; i++)
        g_W16[(size_t)(ta.outRow[m] + n0 + ty + 8 * i) * HD + k0 + tx] =
            __float2half_rn(t[tx][ty + 8 * i]);
}

// ---------------- elementwise epilogues ----------------
__device__ __forceinline__ float sigm(float x) { return 1.f / (1.f + expf(-x)); }

__global__ void epi1_kernel(const float* __restrict__ h, const float* __restrict__ g,
                            float* __restrict__ hnew) {
    size_t e0 = ((size_t)blockIdx.x * blockDim.x + threadIdx.x) * 4;
    size_t b = e0 >> 11, j = e0 & 2047;
    const float* row = g_S1 + b * 8192 + j;
    float4 zp = *(const float4*)(row);
    float4 rp = *(const float4*)(row + 2048);
    float4 up = *(const float4*)(row + 4096);
    float4 cp = *(const float4*)(row + 6144);
    float4 hv = *(const float4*)(h + e0);
    float4 gv = *(const float4*)(g + e0);
    float4 hn, hd;
#define DO1(f)                                                     \
    {                                                              \
        float z = sigm(zp.f), r = sigm(rp.f), uu = sigm(up.f);     \
        float cand = tanhf(cp.f + r * hv.f + uu * gv.f);           \
        hn.f = (1.f - z) * hv.f + z * cand;                        \
        hd.f = hn.f - hv.f;                                        \
    }
    DO1(x) DO1(y) DO1(z) DO1(w)
#undef DO1
    *(float4*)(hnew + e0) = hn;
    __half2* hdp = (__half2*)(g_hd16 + e0);
    hdp[0] = __floats2half2_rn(hd.x, hd.y);
    hdp[1] = __floats2half2_rn(hd.z, hd.w);
}

__global__ void epi2_kernel(const float* __restrict__ g, float* __restrict__ gnew) {
    size_t e0 = ((size_t)blockIdx.x * blockDim.x + threadIdx.x) * 4;
    size_t b = e0 >> 11, j = e0 & 2047;
    const float* row = g_S2 + b * 6144 + j;
    float4 zp = *(const float4*)(row);
    float4 rp = *(const float4*)(row + 2048);
    float4 cp = *(const float4*)(row + 4096);
    float4 gv = *(const float4*)(g + e0);
    float4 gn;
#define DO2(f)                                       \
    {                                                \
        float z = sigm(zp.f), r = sigm(rp.f);        \
        float cand = tanhf(cp.f + r * gv.f);         \
        gn.f = (1.f - z) * gv.f + z * cand;          \
    }
    DO2(x) DO2(y) DO2(z) DO2(w)
#undef DO2
    *(float4*)(gnew + e0) = gn;
}

// ---------------- host ----------------
extern "C" void kernel_launch(void* const* d_in, const int* in_sizes, int n_in,
                              void* d_out, int out_size) {
    (void)in_sizes; (void)n_in; (void)out_size;
    const float* x   = (const float*)d_in[0];
    const float* h   = (const float*)d_in[1];
    const float* g   = (const float*)d_in[2];
    const float* Wx  = (const float*)d_in[3];
    const float* bx  = (const float*)d_in[4];
    const float* Wh  = (const float*)d_in[5];
    const float* bh  = (const float*)d_in[6];
    const float* Wgh = (const float*)d_in[7];
    const float* bgh = (const float*)d_in[8];
    const float* Whd = (const float*)d_in[9];
    const float* bhd = (const float*)d_in[10];
    const float* Wg  = (const float*)d_in[11];
    const float* bg  = (const float*)d_in[12];

    float* out  = (float*)d_out;
    float* hnew = out;
    float* gnew = out + (size_t)BDIM * HD;

    void *pS1, *pS2, *pX, *pH, *pG, *pHd, *pW;
    cudaGetSymbolAddress(&pS1, g_S1);
    cudaGetSymbolAddress(&pS2, g_S2);
    cudaGetSymbolAddress(&pX, g_x16);
    cudaGetSymbolAddress(&pH, g_h16);
    cudaGetSymbolAddress(&pG, g_g16);
    cudaGetSymbolAddress(&pHd, g_hd16);
    cudaGetSymbolAddress(&pW, g_W16);

    cudaFuncSetAttribute(gemm_f16_kernel, cudaFuncAttributeMaxDynamicSharedMemorySize,
                         SMEM_BYTES);

    const int H = HD;
    const int RWx = 0, RWh = 8192, RWgh = 14336, RWhd = 20480, RWg = 26624;

    // 1) activations -> fp16
    actconv_kernel<<<dim3((unsigned)((size_t)BDIM * HD / 4 / 256), 3), 256>>>(x, h, g);

    // 2) weights -> transposed fp16
    {
        TArgs ta;
        const float* Ws[5] = {Wx, Wh, Wgh, Whd, Wg};
        int lds[5] = {4 * H, 3 * H, 3 * H, 3 * H, 2 * H};
        int nts[5] = {256, 192, 192, 192, 128};
        int orow[5] = {RWx, RWh, RWgh, RWhd, RWg};
        for (int i = 0; i < 5; i++) {
            ta.W[i] = Ws[i]; ta.ldw[i] = lds[i]; ta.ntiles[i] = nts[i]; ta.outRow[i] = orow[i];
        }
        wtrans_kernel<<<dim3(960, 64), dim3(32, 8)>>>(ta);
    }

    // 3) stage-1 GEMM: S1 = [z | r | u | cand_x], ldc 8192
    {
        GArgs a;
        a.C = (float*)pS1; a.ldc = 8192;
        const __half* x16 = (const __half*)pX;
        const __half* h16 = (const __half*)pH;
        const __half* g16 = (const __half*)pG;
        int nA[4] = {3, 3, 3, 1};
        const __half* A[4][3] = {{x16, h16, g16}, {x16, h16, g16}, {x16, h16, g16},
                                 {x16, x16, x16}};
        int WR[4][3] = {{RWx, RWh, RWgh},
                        {RWx + H, RWh + H, RWgh + H},
                        {RWx + 3 * H, RWh + 2 * H, RWgh + 2 * H},
                        {RWx + 2 * H, 0, 0}};
        const float* Bp[4][3] = {{bx, bh, bgh},
                                 {bx + H, bh + H, bgh + H},
                                 {bx + 3 * H, bh + 2 * H, bgh + 2 * H},
                                 {bx + 2 * H, bx, bx}};
        for (int i = 0; i < 4; i++) {
            a.nA[i] = nA[i];
            for (int j = 0; j < 3; j++) {
                a.A[i][j] = A[i][j]; a.wrow[i][j] = WR[i][j]; a.bias[i][j] = Bp[i][j];
            }
        }
        gemm_f16_kernel<<<dim3(64, 64), 256, SMEM_BYTES>>>(a, (const __half*)pW);
    }

    unsigned epiBlocks = (unsigned)(((size_t)BDIM * HD / 4) / 256);
    epi1_kernel<<<epiBlocks, 256>>>(h, g, hnew);

    // 4) stage-2 GEMM: S2 = [z2 | r2 | cand2], ldc 6144
    {
        GArgs a;
        a.C = (float*)pS2; a.ldc = 6144;
        const __half* hd16 = (const __half*)pHd;
        const __half* g16 = (const __half*)pG;
        int nA[4] = {2, 2, 1, 1};
        const __half* A[4][3] = {{hd16, g16, hd16}, {hd16, g16, hd16},
                                 {hd16, hd16, hd16}, {hd16, hd16, hd16}};
        int WR[4][3] = {{RWhd, RWg, 0},
                        {RWhd + H, RWg + H, 0},
                        {RWhd + 2 * H, 0, 0},
                        {0, 0, 0}};
        const float* Bp[4][3] = {{bhd, bg, bhd},
                                 {bhd + H, bg + H, bhd},
                                 {bhd + 2 * H, bhd, bhd},
                                 {bhd, bhd, bhd}};
        for (int i = 0; i < 4; i++) {
            a.nA[i] = nA[i];
            for (int j = 0; j < 3; j++) {
                a.A[i][j] = A[i][j]; a.wrow[i][j] = WR[i][j]; a.bias[i][j] = Bp[i][j];
            }
        }
        gemm_f16_kernel<<<dim3(64, 48), 256, SMEM_BYTES>>>(a, (const __half*)pW);
    }

    epi2_kernel<<<epiBlocks, 256>>>(g, gnew);
}

// round 9
// speedup vs baseline: 2.2328x; 1.0796x over previous
#include <cuda_runtime.h>
#include <cuda_fp16.h>
#include <stdint.h>
#include <math.h>

#define HD   2048
#define BDIM 8192
#define BK   64
#define NST  3
#define A_WORDS 4096            // 128 rows * 32 words (word = 2 fp16)
#define B_WORDS 4096            // 128 rows * 32 words
#define SMEM_WORDS (NST * (A_WORDS + B_WORDS))
#define SMEM_BYTES (SMEM_WORDS * 4)   // 98304

// ---------------- device scratch ----------------
__device__ float  g_S1[(size_t)BDIM * 8192];    // [z | r | u | cand_x]
__device__ float  g_S2[(size_t)BDIM * 6144];    // [z2 | r2 | cand2]
__device__ __half g_x16[(size_t)BDIM * HD];
__device__ __half g_h16[(size_t)BDIM * HD];
__device__ __half g_g16[(size_t)BDIM * HD];
__device__ __half g_hd16[(size_t)BDIM * HD];
__device__ __half g_W16[(size_t)30720 * HD];    // all weights, transposed to [N][K]

// ---------------- PTX helpers ----------------
#define CP_ASYNC(dst, src) \
    asm volatile("cp.async.cg.shared.global [%0], [%1], 16;" :: "r"(dst), "l"(src))
#define CP_COMMIT() asm volatile("cp.async.commit_group;" ::: "memory")
#define CP_WAIT(n)  asm volatile("cp.async.wait_group %0;" :: "n"(n) : "memory")

#define LDMX4(r0, r1, r2, r3, addr)                                            \
    asm volatile("ldmatrix.sync.aligned.m8n8.x4.shared.b16 {%0,%1,%2,%3}, [%4];" \
                 : "=r"(r0), "=r"(r1), "=r"(r2), "=r"(r3) : "r"(addr))

__device__ __forceinline__ void mma16(float c[4], const uint32_t a[4], const uint32_t b[2]) {
    asm volatile(
        "mma.sync.aligned.m16n8k16.row.col.f32.f16.f16.f32 "
        "{%0,%1,%2,%3}, {%4,%5,%6,%7}, {%8,%9}, {%0,%1,%2,%3};\n"
        : "+f"(c[0]), "+f"(c[1]), "+f"(c[2]), "+f"(c[3])
        : "r"(a[0]), "r"(a[1]), "r"(a[2]), "r"(a[3]), "r"(b[0]), "r"(b[1]));
}

// swizzled word index: row = 32 words (128B), 16B chunk ch in 0..7
__device__ __forceinline__ int swz(int r, int ch) {
    return r * 32 + ((ch ^ (r & 7)) << 2);
}

// ---------------- GEMM args ----------------
struct GArgs {
    float* C;
    long long ldc;
    int nA[4];
    const __half* A[4][3];     // fp16 activations [8192][2048]
    int wrow[4][3];            // absolute row offset into g_W16
    const float* bias[4][3];
};

// grid: x = M tiles (64), y = N tiles. blk = y>>4 (gate block), nloc = (y&15)*128
__global__ __launch_bounds__(256, 2)
void gemm_f16_kernel(const __grid_constant__ GArgs args, const __half* __restrict__ WB) {
    extern __shared__ uint32_t sm[];
    uint32_t* smA = sm;                       // [NST][A_WORDS]
    uint32_t* smB = sm + NST * A_WORDS;       // [NST][B_WORDS]
    const uint32_t smA0 = (uint32_t)__cvta_generic_to_shared(smA);
    const uint32_t smB0 = (uint32_t)__cvta_generic_to_shared(smB);

    const int tid  = threadIdx.x;
    const int lane = tid & 31;
    const int warp = tid >> 5;
    const int wm = warp & 1;     // 2 warps along M (64 rows)
    const int wn = warp >> 1;    // 4 warps along N (32 cols)

    const int m0   = blockIdx.x << 7;
    const int blk  = blockIdx.y >> 4;
    const int nloc = (blockIdx.y & 15) << 7;
    const int nA   = args.nA[blk];
    const int iters = nA << 5;                // nA * (2048/64)

    const __half* Ap[3];
    int wr[3];
#pragma unroll
    for (int a = 0; a < 3; a++) { Ap[a] = args.A[blk][a]; wr[a] = args.wrow[blk][a]; }

    float acc[4][4][4];
#pragma unroll
    for (int i = 0; i < 4; i++)
#pragma unroll
        for (int j = 0; j < 4; j++)
#pragma unroll
            for (int k = 0; k < 4; k++) acc[i][j][k] = 0.f;

    const int r4 = tid >> 3;     // 0..31
    const int ch = tid & 7;      // 16B chunk within 128B row

    auto load_stage = [&](int it) {
        const int s = it % NST;
        const int a = it >> 5;
        const int k0 = (it & 31) << 6;
        uint32_t* dA = smA + s * A_WORDS;
        uint32_t* dB = smB + s * B_WORDS;
        const __half* Ab = Ap[a];
#pragma unroll
        for (int i = 0; i < 4; i++) {
            const int r = r4 + (i << 5);
            uint32_t dst = (uint32_t)__cvta_generic_to_shared(dA + swz(r, ch));
            CP_ASYNC(dst, Ab + (size_t)(m0 + r) * HD + k0 + ch * 8);
        }
        const size_t wbase = (size_t)(wr[a] + nloc) * HD + k0 + ch * 8;
#pragma unroll
        for (int i = 0; i < 4; i++) {
            const int r = r4 + (i << 5);
            uint32_t dst = (uint32_t)__cvta_generic_to_shared(dB + swz(r, ch));
            CP_ASYNC(dst, WB + wbase + (size_t)r * HD);
        }
        CP_COMMIT();
    };

    // ldmatrix per-lane geometry (constant across iterations)
    const int arow = wm * 64 + (lane & 15);      // + mt*16
    const int acsel = lane >> 4;                 // 0: k-lo 16B, 1: k-hi
    const int bnrow = wn * 32 + ((lane & 16) >> 1) + (lane & 7);  // + np*16
    const int bcsel = (lane >> 3) & 1;

    auto compute = [&](int s) {
        const uint32_t a_base = smA0 + (s * A_WORDS) * 4;
        const uint32_t b_base = smB0 + (s * B_WORDS) * 4;
#pragma unroll
        for (int ks = 0; ks < 4; ks++) {
            uint32_t af[4][4], bf[4][2];
#pragma unroll
            for (int mt = 0; mt < 4; mt++) {
                const int r = arow + mt * 16;
                const int c = (2 * ks + acsel) ^ (r & 7);
                const uint32_t addr = a_base + (r * 32 + (c << 2)) * 4;
                LDMX4(af[mt][0], af[mt][1], af[mt][2], af[mt][3], addr);
            }
#pragma unroll
            for (int np = 0; np < 2; np++) {
                const int n = bnrow + np * 16;
                const int c = (2 * ks + bcsel) ^ (n & 7);
                const uint32_t addr = b_base + (n * 32 + (c << 2)) * 4;
                LDMX4(bf[2 * np][0], bf[2 * np][1], bf[2 * np + 1][0], bf[2 * np + 1][1],
                      addr);
            }
#pragma unroll
            for (int mt = 0; mt < 4; mt++)
#pragma unroll
                for (int nt = 0; nt < 4; nt++)
                    mma16(acc[mt][nt], af[mt], bf[nt]);
        }
    };

    load_stage(0);
    load_stage(1);

#pragma unroll 1
    for (int it = 0; it < iters; it++) {
        CP_WAIT(1);
        __syncthreads();
        if (it + 2 < iters) load_stage(it + 2);
        else CP_COMMIT();   // dummy group keeps wait_group(1) semantics exact at tail
        compute(it % NST);
    }

    // epilogue: bias + store fp32
    const int tig = lane & 3;
    const int gid = lane >> 2;
    const int cbase = blockIdx.y << 7;
#pragma unroll
    for (int nt = 0; nt < 4; nt++) {
        const int cl = wn * 32 + nt * 8 + 2 * tig;
        float bs0 = 0.f, bs1 = 0.f;
        for (int a = 0; a < nA; a++) {
            bs0 += args.bias[blk][a][nloc + cl];
            bs1 += args.bias[blk][a][nloc + cl + 1];
        }
#pragma unroll
        for (int mt = 0; mt < 4; mt++) {
            const int r = m0 + wm * 64 + mt * 16 + gid;
            float2 v0 = make_float2(acc[mt][nt][0] + bs0, acc[mt][nt][1] + bs1);
            float2 v1 = make_float2(acc[mt][nt][2] + bs0, acc[mt][nt][3] + bs1);
            *(float2*)(args.C + (size_t)r * args.ldc + cbase + cl) = v0;
            *(float2*)(args.C + (size_t)(r + 8) * args.ldc + cbase + cl) = v1;
        }
    }
}

// ---------------- prep: activations fp32 -> fp16 ----------------
__global__ void actconv_kernel(const float* __restrict__ x, const float* __restrict__ h,
                               const float* __restrict__ g) {
    const float* src = (blockIdx.y == 0) ? x : (blockIdx.y == 1) ? h : g;
    __half* dst = (blockIdx.y == 0) ? g_x16 : (blockIdx.y == 1) ? g_h16 : g_g16;
    size_t i = ((size_t)blockIdx.x * blockDim.x + threadIdx.x) * 4;
    float4 v = *(const float4*)(src + i);
    __half2* d = (__half2*)(dst + i);
    d[0] = __floats2half2_rn(v.x, v.y);
    d[1] = __floats2half2_rn(v.z, v.w);
}

// ---------------- prep: weights fp32 [K][N] -> fp16 [N][K] in g_W16 ----------------
struct TArgs {
    const float* W[5];
    int ldw[5];
    int ntiles[5];    // n-dim 32-tiles per matrix
    int outRow[5];    // row offset in g_W16
};
__global__ void wtrans_kernel(const __grid_constant__ TArgs ta) {
    __shared__ float t[32][33];
    int xt = blockIdx.x, m = 0;
    while (xt >= ta.ntiles[m]) { xt -= ta.ntiles[m]; m++; }
    const float* W = ta.W[m];
    const int ldw = ta.ldw[m];
    const int n0 = xt << 5, k0 = blockIdx.y << 5;
    const int tx = threadIdx.x, ty = threadIdx.y;
#pragma unroll
    for (int i = 0; i < 4; i++)
        t[ty + 8 * i][tx] = W[(size_t)(k0 + ty + 8 * i) * ldw + n0 + tx];
    __syncthreads();
#pragma unroll
    for (int i = 0; i < 4; i++)
        g_W16[(size_t)(ta.outRow[m] + n0 + ty + 8 * i) * HD + k0 + tx] =
            __float2half_rn(t[tx][ty + 8 * i]);
}

// ---------------- elementwise epilogues ----------------
__device__ __forceinline__ float sigm(float x) { return 1.f / (1.f + expf(-x)); }

__global__ void epi1_kernel(const float* __restrict__ h, const float* __restrict__ g,
                            float* __restrict__ hnew) {
    size_t e0 = ((size_t)blockIdx.x * blockDim.x + threadIdx.x) * 4;
    size_t b = e0 >> 11, j = e0 & 2047;
    const float* row = g_S1 + b * 8192 + j;
    float4 zp = *(const float4*)(row);
    float4 rp = *(const float4*)(row + 2048);
    float4 up = *(const float4*)(row + 4096);
    float4 cp = *(const float4*)(row + 6144);
    float4 hv = *(const float4*)(h + e0);
    float4 gv = *(const float4*)(g + e0);
    float4 hn, hd;
#define DO1(f)                                                     \
    {                                                              \
        float z = sigm(zp.f), r = sigm(rp.f), uu = sigm(up.f);     \
        float cand = tanhf(cp.f + r * hv.f + uu * gv.f);           \
        hn.f = (1.f - z) * hv.f + z * cand;                        \
        hd.f = hn.f - hv.f;                                        \
    }
    DO1(x) DO1(y) DO1(z) DO1(w)
#undef DO1
    *(float4*)(hnew + e0) = hn;
    __half2* hdp = (__half2*)(g_hd16 + e0);
    hdp[0] = __floats2half2_rn(hd.x, hd.y);
    hdp[1] = __floats2half2_rn(hd.z, hd.w);
}

__global__ void epi2_kernel(const float* __restrict__ g, float* __restrict__ gnew) {
    size_t e0 = ((size_t)blockIdx.x * blockDim.x + threadIdx.x) * 4;
    size_t b = e0 >> 11, j = e0 & 2047;
    const float* row = g_S2 + b * 6144 + j;
    float4 zp = *(const float4*)(row);
    float4 rp = *(const float4*)(row + 2048);
    float4 cp = *(const float4*)(row + 4096);
    float4 gv = *(const float4*)(g + e0);
    float4 gn;
#define DO2(f)                                       \
    {                                                \
        float z = sigm(zp.f), r = sigm(rp.f);        \
        float cand = tanhf(cp.f + r * gv.f);         \
        gn.f = (1.f - z) * gv.f + z * cand;          \
    }
    DO2(x) DO2(y) DO2(z) DO2(w)
#undef DO2
    *(float4*)(gnew + e0) = gn;
}

// ---------------- host ----------------
extern "C" void kernel_launch(void* const* d_in, const int* in_sizes, int n_in,
                              void* d_out, int out_size) {
    (void)in_sizes; (void)n_in; (void)out_size;
    const float* x   = (const float*)d_in[0];
    const float* h   = (const float*)d_in[1];
    const float* g   = (const float*)d_in[2];
    const float* Wx  = (const float*)d_in[3];
    const float* bx  = (const float*)d_in[4];
    const float* Wh  = (const float*)d_in[5];
    const float* bh  = (const float*)d_in[6];
    const float* Wgh = (const float*)d_in[7];
    const float* bgh = (const float*)d_in[8];
    const float* Whd = (const float*)d_in[9];
    const float* bhd = (const float*)d_in[10];
    const float* Wg  = (const float*)d_in[11];
    const float* bg  = (const float*)d_in[12];

    float* out  = (float*)d_out;
    float* hnew = out;
    float* gnew = out + (size_t)BDIM * HD;

    void *pS1, *pS2, *pX, *pH, *pG, *pHd, *pW;
    cudaGetSymbolAddress(&pS1, g_S1);
    cudaGetSymbolAddress(&pS2, g_S2);
    cudaGetSymbolAddress(&pX, g_x16);
    cudaGetSymbolAddress(&pH, g_h16);
    cudaGetSymbolAddress(&pG, g_g16);
    cudaGetSymbolAddress(&pHd, g_hd16);
    cudaGetSymbolAddress(&pW, g_W16);

    cudaFuncSetAttribute(gemm_f16_kernel, cudaFuncAttributeMaxDynamicSharedMemorySize,
                         SMEM_BYTES);

    const int H = HD;
    const int RWx = 0, RWh = 8192, RWgh = 14336, RWhd = 20480, RWg = 26624;

    // 1) activations -> fp16
    actconv_kernel<<<dim3((unsigned)((size_t)BDIM * HD / 4 / 256), 3), 256>>>(x, h, g);

    // 2) weights -> transposed fp16
    {
        TArgs ta;
        const float* Ws[5] = {Wx, Wh, Wgh, Whd, Wg};
        int lds[5] = {4 * H, 3 * H, 3 * H, 3 * H, 2 * H};
        int nts[5] = {256, 192, 192, 192, 128};
        int orow[5] = {RWx, RWh, RWgh, RWhd, RWg};
        for (int i = 0; i < 5; i++) {
            ta.W[i] = Ws[i]; ta.ldw[i] = lds[i]; ta.ntiles[i] = nts[i]; ta.outRow[i] = orow[i];
        }
        wtrans_kernel<<<dim3(960, 64), dim3(32, 8)>>>(ta);
    }

    // 3) stage-1 GEMM: S1 = [z | r | u | cand_x], ldc 8192
    {
        GArgs a;
        a.C = (float*)pS1; a.ldc = 8192;
        const __half* x16 = (const __half*)pX;
        const __half* h16 = (const __half*)pH;
        const __half* g16 = (const __half*)pG;
        int nA[4] = {3, 3, 3, 1};
        const __half* A[4][3] = {{x16, h16, g16}, {x16, h16, g16}, {x16, h16, g16},
                                 {x16, x16, x16}};
        int WR[4][3] = {{RWx, RWh, RWgh},
                        {RWx + H, RWh + H, RWgh + H},
                        {RWx + 3 * H, RWh + 2 * H, RWgh + 2 * H},
                        {RWx + 2 * H, 0, 0}};
        const float* Bp[4][3] = {{bx, bh, bgh},
                                 {bx + H, bh + H, bgh + H},
                                 {bx + 3 * H, bh + 2 * H, bgh + 2 * H},
                                 {bx + 2 * H, bx, bx}};
        for (int i = 0; i < 4; i++) {
            a.nA[i] = nA[i];
            for (int j = 0; j < 3; j++) {
                a.A[i][j] = A[i][j]; a.wrow[i][j] = WR[i][j]; a.bias[i][j] = Bp[i][j];
            }
        }
        gemm_f16_kernel<<<dim3(64, 64), 256, SMEM_BYTES>>>(a, (const __half*)pW);
    }

    unsigned epiBlocks = (unsigned)(((size_t)BDIM * HD / 4) / 256);
    epi1_kernel<<<epiBlocks, 256>>>(h, g, hnew);

    // 4) stage-2 GEMM: S2 = [z2 | r2 | cand2], ldc 6144
    {
        GArgs a;
        a.C = (float*)pS2; a.ldc = 6144;
        const __half* hd16 = (const __half*)pHd;
        const __half* g16 = (const __half*)pG;
        int nA[4] = {2, 2, 1, 1};
        const __half* A[4][3] = {{hd16, g16, hd16}, {hd16, g16, hd16},
                                 {hd16, hd16, hd16}, {hd16, hd16, hd16}};
        int WR[4][3] = {{RWhd, RWg, 0},
                        {RWhd + H, RWg + H, 0},
                        {RWhd + 2 * H, 0, 0},
                        {0, 0, 0}};
        const float* Bp[4][3] = {{bhd, bg, bhd},
                                 {bhd + H, bg + H, bhd},
                                 {bhd + 2 * H, bhd, bhd},
                                 {bhd, bhd, bhd}};
        for (int i = 0; i < 4; i++) {
            a.nA[i] = nA[i];
            for (int j = 0; j < 3; j++) {
                a.A[i][j] = A[i][j]; a.wrow[i][j] = WR[i][j]; a.bias[i][j] = Bp[i][j];
            }
        }
        gemm_f16_kernel<<<dim3(64, 48), 256, SMEM_BYTES>>>(a, (const __half*)pW);
    }

    epi2_kernel<<<epiBlocks, 256>>>(g, gnew);
}